// round 9
// baseline (speedup 1.0000x reference)
#include <cuda_runtime.h>
#include <stdint.h>

// Shapes (fixed by the problem): k (1,32,64,256,256) fp32, mask (64,256,256) int32
#define ALPHA 0.5f
#define BETA  0.25f

constexpr int NC = 32;
constexpr int NT = 64;
constexpr int NX = 256;
constexpr int NY = 256;
constexpr int SPATIAL = NX * NY;              // 65536 elems per t-slice
constexpr long PLANE  = (long)NT * SPATIAL;   // elems per channel

// 4 MiB selector scratch: 0 = zero, 1 = k[t], 2 = ALPHA*k[t-1], 3 = BETA*k[t+1]
__device__ unsigned char g_sel[NT * SPATIAL];

// ---------------------------------------------------------------------------
// Kernel 1: mask (64,256,256) int32 -> selector byte per site.
// m1 = !m_cur & m_prev          -> ALPHA * k_prev   (sel 2)
// m3 = m_next & !(m_prev|m_cur) -> BETA  * k_next   (sel 3)
// m_cur                         -> k                (sel 1)
// (mutually exclusive by construction)
// ---------------------------------------------------------------------------
__global__ void sel_kernel(const int* __restrict__ mask) {
    int i = blockIdx.x * blockDim.x + threadIdx.x;
    if (i >= NT * SPATIAL) return;
    int t = i / SPATIAL;
    int cur  = mask[i];
    int prev = (t > 0)      ? mask[i - SPATIAL] : 0;
    int next = (t < NT - 1) ? mask[i + SPATIAL] : 0;
    unsigned char s = cur ? 1u : (prev ? 2u : (next ? 3u : 0u));
    g_sel[i] = s;
}

// ---------------------------------------------------------------------------
// Kernel 2: each thread owns (c, x, 4 consecutive y) and walks t with
// register-carried kp/kc/kn float4 -> every k element read exactly once.
// ---------------------------------------------------------------------------
__global__ __launch_bounds__(256)
void apply_kernel(const float* __restrict__ k, float* __restrict__ out) {
    constexpr int NY4 = NY / 4;                       // 64 float4 per row
    int tid = blockIdx.x * blockDim.x + threadIdx.x;  // over NC*NX*NY4
    if (tid >= NC * NX * NY4) return;

    int y4 = tid % NY4;
    int xc = tid / NY4;
    int x  = xc % NX;
    int c  = xc / NX;

    long base  = (long)c * PLANE + (long)x * NY + (long)y4 * 4; // k/out index @ t=0
    long sbase = (long)x * NY + (long)y4 * 4;                   // selector index @ t=0

    float4 kp = make_float4(0.f, 0.f, 0.f, 0.f);
    float4 kc = __ldcs(reinterpret_cast<const float4*>(k + base));

    #pragma unroll 4
    for (int t = 0; t < NT; ++t) {
        float4 kn;
        if (t + 1 < NT) {
            kn = __ldcs(reinterpret_cast<const float4*>(k + base + (long)(t + 1) * SPATIAL));
        } else {
            kn = make_float4(0.f, 0.f, 0.f, 0.f);
        }

        // selector stays L2-resident (4 MiB, reused across 32 channels): default caching
        uchar4 s = *reinterpret_cast<const uchar4*>(g_sel + sbase + (long)t * SPATIAL);

        float4 o;
        o.x = (s.x == 1) ? kc.x : (s.x == 2) ? ALPHA * kp.x : (s.x == 3) ? BETA * kn.x : 0.f;
        o.y = (s.y == 1) ? kc.y : (s.y == 2) ? ALPHA * kp.y : (s.y == 3) ? BETA * kn.y : 0.f;
        o.z = (s.z == 1) ? kc.z : (s.z == 2) ? ALPHA * kp.z : (s.z == 3) ? BETA * kn.z : 0.f;
        o.w = (s.w == 1) ? kc.w : (s.w == 2) ? ALPHA * kp.w : (s.w == 3) ? BETA * kn.w : 0.f;

        __stcs(reinterpret_cast<float4*>(out + base + (long)t * SPATIAL), o);

        kp = kc;
        kc = kn;
    }
}

extern "C" void kernel_launch(void* const* d_in, const int* in_sizes, int n_in,
                              void* d_out, int out_size) {
    const float* k    = (const float*)d_in[0];
    const int*   mask = (const int*)d_in[1];
    float*       out  = (float*)d_out;

    // Kernel 1: selector bytes (4 MiB)
    {
        int n = NT * SPATIAL;
        int threads = 256;
        int blocks = (n + threads - 1) / threads;
        sel_kernel<<<blocks, threads>>>(mask);
    }

    // Kernel 2: streaming apply
    {
        int n = NC * NX * (NY / 4);       // 524288 threads
        int threads = 256;
        int blocks = (n + threads - 1) / threads;
        apply_kernel<<<blocks, threads>>>(k, out);
    }
}